// round 1
// baseline (speedup 1.0000x reference)
#include <cuda_runtime.h>
#include <cuda_fp16.h>
#include <math.h>

#define L_SEQ 2048
#define H_DIM 2048
#define G3H   6144
#define NCTA  147
#define CHUNK 14      // h elements per CTA (147*14 = 2058 >= 2048)
#define NROWS 42      // 3 gates * CHUNK

// -------- device-global scratch (no allocations allowed) --------
__device__ float        g_gi[(size_t)L_SEQ * G3H];   // 48 MB precomputed input gates
__device__ __half       g_h16[2][H_DIM];             // double-buffered fp16 h broadcast
__device__ unsigned int g_sync;                      // monotonic arrival counter

__global__ void reset_kernel() { g_sync = 0u; }

// ============================================================
// Kernel A: g_gi[t][r] = sum_k x[t][k] * w_ih[r][k] + b_ih[r]
// fp32 GEMM (NT) with packed fma.rn.f32x2 (2 MAC / instr)
// ============================================================
#define BM 64
#define BN 64
#define BK 16

__global__ void __launch_bounds__(256) gemm_gi_kernel(const float* __restrict__ X,
                                                      const float* __restrict__ W,
                                                      const float* __restrict__ bias) {
    __shared__ float As[BK][BM + 4];   // +4 pad: keeps 16B alignment, spreads banks
    __shared__ float Bs[BK][BN + 4];
    const int K = H_DIM;
    const int bm = blockIdx.y * BM;
    const int bn = blockIdx.x * BN;
    const int tid = threadIdx.x;
    const int tm = tid >> 4;          // 0..15
    const int tn = tid & 15;          // 0..15

    unsigned long long c[2][4];
#pragma unroll
    for (int i = 0; i < 2; i++)
#pragma unroll
        for (int j = 0; j < 4; j++) c[i][j] = 0ull;

    const int lrow = tid >> 2;        // 0..63
    const int lk   = (tid & 3) << 2;  // 0,4,8,12

    for (int k0 = 0; k0 < K; k0 += BK) {
        float4 av = *reinterpret_cast<const float4*>(&X[(size_t)(bm + lrow) * K + k0 + lk]);
        float4 bv = *reinterpret_cast<const float4*>(&W[(size_t)(bn + lrow) * K + k0 + lk]);
        As[lk + 0][lrow] = av.x; As[lk + 1][lrow] = av.y;
        As[lk + 2][lrow] = av.z; As[lk + 3][lrow] = av.w;
        Bs[lk + 0][lrow] = bv.x; Bs[lk + 1][lrow] = bv.y;
        Bs[lk + 2][lrow] = bv.z; Bs[lk + 3][lrow] = bv.w;
        __syncthreads();
#pragma unroll
        for (int k = 0; k < BK; k++) {
            float4 a = *reinterpret_cast<const float4*>(&As[k][tm << 2]);
            float4 b = *reinterpret_cast<const float4*>(&Bs[k][tn << 2]);
            unsigned long long a01, a23;
            asm("mov.b64 %0, {%1, %2};" : "=l"(a01) : "r"(__float_as_uint(a.x)), "r"(__float_as_uint(a.y)));
            asm("mov.b64 %0, {%1, %2};" : "=l"(a23) : "r"(__float_as_uint(a.z)), "r"(__float_as_uint(a.w)));
            float bj[4] = {b.x, b.y, b.z, b.w};
#pragma unroll
            for (int j = 0; j < 4; j++) {
                unsigned long long bb;
                asm("mov.b64 %0, {%1, %1};" : "=l"(bb) : "r"(__float_as_uint(bj[j])));
                asm("fma.rn.f32x2 %0, %1, %2, %0;" : "+l"(c[0][j]) : "l"(a01), "l"(bb));
                asm("fma.rn.f32x2 %0, %1, %2, %0;" : "+l"(c[1][j]) : "l"(a23), "l"(bb));
            }
        }
        __syncthreads();
    }
#pragma unroll
    for (int i2 = 0; i2 < 2; i2++) {
#pragma unroll
        for (int j = 0; j < 4; j++) {
            unsigned lo, hi;
            asm("mov.b64 {%0, %1}, %2;" : "=r"(lo), "=r"(hi) : "l"(c[i2][j]));
            int col  = bn + (tn << 2) + j;
            float bs = bias[col];
            int row0 = bm + (tm << 2) + i2 * 2;
            g_gi[(size_t)row0 * G3H + col]       = __uint_as_float(lo) + bs;
            g_gi[(size_t)(row0 + 1) * G3H + col] = __uint_as_float(hi) + bs;
        }
    }
}

// ============================================================
// Kernel B: persistent GRU recurrence.
// 147 CTAs, 256 threads. CTA c owns h[j], j in [14c, 14c+14).
// SMEM: fp16 W_hh slice (rows ordered [r gate jj][z gate jj][n gate jj]),
//       fp16 h broadcast, per-row gh sums, b_hh slice.
// Global barrier each step via monotonic counter.
// ============================================================
#define GRU_SMEM_W   (NROWS * H_DIM * 2)             // 172032
#define GRU_SMEM_H   (H_DIM * 2)                     // 4096
#define GRU_SMEM_TOT (GRU_SMEM_W + GRU_SMEM_H + 64*4 + 64*4)  // 176640 B

__global__ void __launch_bounds__(256, 1) gru_kernel(const float* __restrict__ w_hh,
                                                     const float* __restrict__ b_hh,
                                                     float* __restrict__ out,
                                                     int out_elems) {
    extern __shared__ char smem_raw[];
    __half* sW   = reinterpret_cast<__half*>(smem_raw);
    __half* sH   = reinterpret_cast<__half*>(smem_raw + GRU_SMEM_W);
    float*  sGH  = reinterpret_cast<float*>(smem_raw + GRU_SMEM_W + GRU_SMEM_H);
    float*  sBhh = sGH + 64;

    const int tid   = threadIdx.x;
    const int cta   = blockIdx.x;
    const int jbase = cta * CHUNK;
    const int warp  = tid >> 5;
    const int lane  = tid & 31;

    // ---- prologue: load + convert this CTA's W_hh slice to fp16 SMEM ----
    for (int idx = tid; idx < NROWS * H_DIM; idx += 256) {
        int lrow = idx >> 11;          // 0..41
        int k    = idx & (H_DIM - 1);
        int gate = lrow / CHUNK;
        int jj   = lrow - gate * CHUNK;
        int j    = jbase + jj;
        float v  = (j < H_DIM) ? w_hh[(size_t)(gate * H_DIM + j) * H_DIM + k] : 0.0f;
        sW[idx]  = __float2half(v);
    }
    if (tid < NROWS) {
        int gate = tid / CHUNK;
        int jj   = tid - gate * CHUNK;
        int j    = jbase + jj;
        sBhh[tid] = (j < H_DIM) ? b_hh[gate * H_DIM + j] : 0.0f;
    }
    const int  jglob = jbase + tid;
    const bool owner = (tid < CHUNK) && (jglob < H_DIM);
    float h_own = 0.0f;
    const int nr = (warp < 2) ? 6 : 5;   // rows warp+8*r, r<nr (covers 0..41)
    __syncthreads();

    for (int t = 0; t < L_SEQ; t++) {
        // ---- stage fp16 h_t into SMEM (bypass L1: other SMs wrote it) ----
        if (t > 0) {
            const uint4* src = reinterpret_cast<const uint4*>(&g_h16[t & 1][0]);
            reinterpret_cast<uint4*>(sH)[tid] = __ldcg(src + tid);
        }
        __syncthreads();

        // ---- matvec: gh rows {warp + 8r} ----
        float accf[6];
#pragma unroll
        for (int r = 0; r < 6; r++) accf[r] = 0.0f;
        if (t > 0) {
            const uint4* hp = reinterpret_cast<const uint4*>(sH) + lane;
#pragma unroll
            for (int i = 0; i < 8; i++) {
                uint4 hv = hp[i * 32];
                __half2 h0 = *reinterpret_cast<__half2*>(&hv.x);
                __half2 h1 = *reinterpret_cast<__half2*>(&hv.y);
                __half2 h2 = *reinterpret_cast<__half2*>(&hv.z);
                __half2 h3 = *reinterpret_cast<__half2*>(&hv.w);
#pragma unroll
                for (int r = 0; r < 6; r++) {
                    if (r < nr) {
                        int row = warp + (r << 3);
                        uint4 wv = *(reinterpret_cast<const uint4*>(sW + (row << 11)) + lane + i * 32);
                        __half2 a = __hmul2(*reinterpret_cast<__half2*>(&wv.x), h0);
                        a = __hfma2(*reinterpret_cast<__half2*>(&wv.y), h1, a);
                        a = __hfma2(*reinterpret_cast<__half2*>(&wv.z), h2, a);
                        a = __hfma2(*reinterpret_cast<__half2*>(&wv.w), h3, a);
                        float2 f = __half22float2(a);        // flush to fp32 every 16 MACs
                        accf[r] += f.x + f.y;
                    }
                }
            }
        }
#pragma unroll
        for (int off = 16; off >= 1; off >>= 1) {
#pragma unroll
            for (int r = 0; r < 6; r++)
                accf[r] += __shfl_xor_sync(0xffffffffu, accf[r], off);
        }
        if (lane == 0) {
#pragma unroll
            for (int r = 0; r < 6; r++)
                if (r < nr) sGH[warp + (r << 3)] = accf[r];
        }
        __syncthreads();

        // ---- gates + state update (14 owner threads, fp32 master h) ----
        if (owner) {
            float ghr = sGH[tid]             + sBhh[tid];
            float ghz = sGH[CHUNK + tid]     + sBhh[CHUNK + tid];
            float ghn = sGH[2 * CHUNK + tid] + sBhh[2 * CHUNK + tid];
            const float* gi = g_gi + (size_t)t * G3H;
            float ir = gi[jglob];
            float iz = gi[H_DIM + jglob];
            float in_ = gi[2 * H_DIM + jglob];
            float rg = 1.0f / (1.0f + expf(-(ir + ghr)));
            float zg = 1.0f / (1.0f + expf(-(iz + ghz)));
            float ng = tanhf(in_ + rg * ghn);
            float hn = (1.0f - zg) * ng + zg * h_own;
            h_own = hn;
            out[(size_t)t * H_DIM + jglob] = hn;
            g_h16[(t + 1) & 1][jglob] = __float2half(hn);
            if (t == L_SEQ - 1) {
                size_t base = (size_t)L_SEQ * H_DIM;
                if ((long long)(base + jglob) < out_elems)          out[base + jglob] = hn;
                if ((long long)(base + H_DIM + jglob) < out_elems)  out[base + H_DIM + jglob] = hn;
            }
            __threadfence();   // make h16 visible gpu-wide before arrival
        }
        __syncthreads();

        // ---- chip-wide barrier: monotonic counter ----
        if (tid == 0) {
            asm volatile("red.release.gpu.global.add.u32 [%0], %1;"
                         :: "l"(&g_sync), "r"(1u) : "memory");
            unsigned target = (unsigned)(t + 1) * (unsigned)NCTA;
            unsigned v;
            do {
                asm volatile("ld.acquire.gpu.global.u32 %0, [%1];"
                             : "=r"(v) : "l"(&g_sync) : "memory");
            } while (v < target);
        }
        __syncthreads();
    }
}

// ============================================================
extern "C" void kernel_launch(void* const* d_in, const int* in_sizes, int n_in,
                              void* d_out, int out_size) {
    const float* x    = (const float*)d_in[0];
    const float* w_ih = (const float*)d_in[1];
    const float* w_hh = (const float*)d_in[2];
    const float* b_ih = (const float*)d_in[3];
    const float* b_hh = (const float*)d_in[4];
    float* out = (float*)d_out;

    cudaFuncSetAttribute(gru_kernel, cudaFuncAttributeMaxDynamicSharedMemorySize, GRU_SMEM_TOT);

    reset_kernel<<<1, 1>>>();
    gemm_gi_kernel<<<dim3(G3H / BN, L_SEQ / BM), 256>>>(x, w_ih, b_ih);
    gru_kernel<<<NCTA, 256, GRU_SMEM_TOT>>>(w_hh, b_hh, out, out_size);
}

// round 2
// speedup vs baseline: 1.1740x; 1.1740x over previous
#include <cuda_runtime.h>
#include <cuda_fp16.h>
#include <math.h>

#define L_SEQ 2048
#define H_DIM 2048
#define G3H   6144
#define NCTA  128
#define CHUNK 16      // h elements per CTA (128*16 = 2048 exactly)

// -------- device-global scratch (no allocations allowed) --------
__device__ float        g_gi[(size_t)L_SEQ * G3H];   // 48 MB precomputed input gates
__device__ __half       g_h16[2][H_DIM];             // double-buffered fp16 h broadcast
__device__ unsigned int g_sync;                      // monotonic arrival counter

// ============================================================
// Kernel A: g_gi[t][r] = sum_k x[t][k] * w_ih[r][k] + b_ih[r]
// fp32 GEMM (NT) with packed fma.rn.f32x2 (2 MAC / instr)
// Also resets g_sync (block 0) so no separate reset launch.
// ============================================================
#define BM 64
#define BN 64
#define BK 16

__global__ void __launch_bounds__(256) gemm_gi_kernel(const float* __restrict__ X,
                                                      const float* __restrict__ W,
                                                      const float* __restrict__ bias) {
    if (blockIdx.x == 0 && blockIdx.y == 0 && threadIdx.x == 0) g_sync = 0u;

    __shared__ float As[BK][BM + 4];
    __shared__ float Bs[BK][BN + 4];
    const int K = H_DIM;
    const int bm = blockIdx.y * BM;
    const int bn = blockIdx.x * BN;
    const int tid = threadIdx.x;
    const int tm = tid >> 4;
    const int tn = tid & 15;

    unsigned long long c[2][4];
#pragma unroll
    for (int i = 0; i < 2; i++)
#pragma unroll
        for (int j = 0; j < 4; j++) c[i][j] = 0ull;

    const int lrow = tid >> 2;
    const int lk   = (tid & 3) << 2;

    for (int k0 = 0; k0 < K; k0 += BK) {
        float4 av = *reinterpret_cast<const float4*>(&X[(size_t)(bm + lrow) * K + k0 + lk]);
        float4 bv = *reinterpret_cast<const float4*>(&W[(size_t)(bn + lrow) * K + k0 + lk]);
        As[lk + 0][lrow] = av.x; As[lk + 1][lrow] = av.y;
        As[lk + 2][lrow] = av.z; As[lk + 3][lrow] = av.w;
        Bs[lk + 0][lrow] = bv.x; Bs[lk + 1][lrow] = bv.y;
        Bs[lk + 2][lrow] = bv.z; Bs[lk + 3][lrow] = bv.w;
        __syncthreads();
#pragma unroll
        for (int k = 0; k < BK; k++) {
            float4 a = *reinterpret_cast<const float4*>(&As[k][tm << 2]);
            float4 b = *reinterpret_cast<const float4*>(&Bs[k][tn << 2]);
            unsigned long long a01, a23;
            asm("mov.b64 %0, {%1, %2};" : "=l"(a01) : "r"(__float_as_uint(a.x)), "r"(__float_as_uint(a.y)));
            asm("mov.b64 %0, {%1, %2};" : "=l"(a23) : "r"(__float_as_uint(a.z)), "r"(__float_as_uint(a.w)));
            float bj[4] = {b.x, b.y, b.z, b.w};
#pragma unroll
            for (int j = 0; j < 4; j++) {
                unsigned long long bb;
                asm("mov.b64 %0, {%1, %1};" : "=l"(bb) : "r"(__float_as_uint(bj[j])));
                asm("fma.rn.f32x2 %0, %1, %2, %0;" : "+l"(c[0][j]) : "l"(a01), "l"(bb));
                asm("fma.rn.f32x2 %0, %1, %2, %0;" : "+l"(c[1][j]) : "l"(a23), "l"(bb));
            }
        }
        __syncthreads();
    }
#pragma unroll
    for (int i2 = 0; i2 < 2; i2++) {
#pragma unroll
        for (int j = 0; j < 4; j++) {
            unsigned lo, hi;
            asm("mov.b64 {%0, %1}, %2;" : "=r"(lo), "=r"(hi) : "l"(c[i2][j]));
            int col  = bn + (tn << 2) + j;
            float bs = bias[col];
            int row0 = bm + (tm << 2) + i2 * 2;
            g_gi[(size_t)row0 * G3H + col]       = __uint_as_float(lo) + bs;
            g_gi[(size_t)(row0 + 1) * G3H + col] = __uint_as_float(hi) + bs;
        }
    }
}

// ============================================================
// Kernel B: persistent GRU recurrence, register-resident weights.
// 128 CTAs x 256 threads. Warp w of CTA c owns j0=16c+2w, j1=j0+1,
// all 3 gates (6 rows). Weights live in 192 half2 registers/lane.
// Per step: poll -> ldcg h -> reg matvec -> butterfly reduce ->
// lanes 0/1 compute gates -> store -> bar -> red.release arrive.
// ============================================================
__device__ __forceinline__ __half2 u2h2(unsigned u) {
    return *reinterpret_cast<__half2*>(&u);
}

__global__ void __launch_bounds__(256, 1) gru_kernel(const float* __restrict__ w_hh,
                                                     const float* __restrict__ b_hh,
                                                     float* __restrict__ out,
                                                     int out_elems) {
    const int tid  = threadIdx.x;
    const int warp = tid >> 5;
    const int lane = tid & 31;
    const int j0   = blockIdx.x * CHUNK + 2 * warp;

    // ---- prologue: weights into registers (fp16) ----
    // w[r][i][c]: row r (0..2: gates r,z,n of j0; 3..5: of j1),
    // i = k-batch, lane covers halfs [ (i*32+lane)*8, +8 )
    __half2 w[6][8][4];
#pragma unroll
    for (int r = 0; r < 6; r++) {
        int j    = (r < 3) ? j0 : (j0 + 1);
        int gate = (r < 3) ? r : (r - 3);
        const float* wr = w_hh + (size_t)(gate * H_DIM + j) * H_DIM;
#pragma unroll
        for (int i = 0; i < 8; i++) {
            int k = (i * 32 + lane) * 8;
            float4 a = *reinterpret_cast<const float4*>(wr + k);
            float4 b = *reinterpret_cast<const float4*>(wr + k + 4);
            w[r][i][0] = __floats2half2_rn(a.x, a.y);
            w[r][i][1] = __floats2half2_rn(a.z, a.w);
            w[r][i][2] = __floats2half2_rn(b.x, b.y);
            w[r][i][3] = __floats2half2_rn(b.z, b.w);
        }
    }

    // lanes 0/1 own j0 / j1
    const int myj = j0 + lane;            // valid for lane < 2
    float bhr = 0.f, bhz = 0.f, bhn = 0.f, h_own = 0.f;
    if (lane < 2) {
        bhr = b_hh[myj];
        bhz = b_hh[H_DIM + myj];
        bhn = b_hh[2 * H_DIM + myj];
    }
    __syncthreads();

    for (int t = 0; t < L_SEQ; t++) {
        // ---- chip-wide wait for step t's h to be published ----
        if (t > 0) {
            if (tid == 0) {
                unsigned target = (unsigned)t << 7;   // t * 128
                unsigned v;
                do {
                    asm volatile("ld.acquire.gpu.global.u32 %0, [%1];"
                                 : "=r"(v) : "l"(&g_sync) : "memory");
                } while (v < target);
            }
            __syncthreads();
        }

        // ---- prefetch gi (independent of matvec; hides L2 latency) ----
        float ir = 0.f, iz = 0.f, inn = 0.f;
        if (lane < 2) {
            const float* gp = g_gi + (size_t)t * G3H + myj;
            ir  = gp[0];
            iz  = gp[H_DIM];
            inn = gp[2 * H_DIM];
        }

        // ---- matvec: 6 rows, weights in regs, h via ldcg ----
        float accf[6] = {0.f, 0.f, 0.f, 0.f, 0.f, 0.f};
        if (t > 0) {
            const uint4* hb = reinterpret_cast<const uint4*>(&g_h16[t & 1][0]) + lane;
            uint4 ha = __ldcg(hb);
            uint4 hc = __ldcg(hb + 32);
#pragma unroll
            for (int ib = 0; ib < 4; ib++) {
                uint4 na, nc;
                if (ib < 3) {
                    na = __ldcg(hb + (2 * ib + 2) * 32);
                    nc = __ldcg(hb + (2 * ib + 3) * 32);
                }
                __half2 a0 = u2h2(ha.x), a1 = u2h2(ha.y), a2 = u2h2(ha.z), a3 = u2h2(ha.w);
                __half2 c0 = u2h2(hc.x), c1 = u2h2(hc.y), c2 = u2h2(hc.z), c3 = u2h2(hc.w);
#pragma unroll
                for (int r = 0; r < 6; r++) {
                    __half2 s = __hmul2(w[r][2 * ib][0], a0);
                    s = __hfma2(w[r][2 * ib][1], a1, s);
                    s = __hfma2(w[r][2 * ib][2], a2, s);
                    s = __hfma2(w[r][2 * ib][3], a3, s);
                    s = __hfma2(w[r][2 * ib + 1][0], c0, s);
                    s = __hfma2(w[r][2 * ib + 1][1], c1, s);
                    s = __hfma2(w[r][2 * ib + 1][2], c2, s);
                    s = __hfma2(w[r][2 * ib + 1][3], c3, s);
                    float2 f = __half22float2(s);     // flush to fp32 every 16 MACs
                    accf[r] += f.x + f.y;
                }
                ha = na; hc = nc;
            }
        }

        // ---- butterfly reduce: all lanes end with all 6 sums ----
#pragma unroll
        for (int off = 16; off; off >>= 1) {
#pragma unroll
            for (int r = 0; r < 6; r++)
                accf[r] += __shfl_xor_sync(0xffffffffu, accf[r], off);
        }

        // ---- gates + state update (lanes 0,1 per warp) ----
        if (lane < 2) {
            int rb = lane * 3;
            float ghr = accf[rb + 0] + bhr;
            float ghz = accf[rb + 1] + bhz;
            float ghn = accf[rb + 2] + bhn;
            float rg = 1.0f / (1.0f + expf(-(ir + ghr)));
            float zg = 1.0f / (1.0f + expf(-(iz + ghz)));
            float ng = tanhf(inn + rg * ghn);
            float hn = (1.0f - zg) * ng + zg * h_own;
            h_own = hn;
            out[(size_t)t * H_DIM + myj] = hn;
            g_h16[(t + 1) & 1][myj] = __float2half(hn);
            if (t == L_SEQ - 1) {
                size_t base = (size_t)L_SEQ * H_DIM;
                if ((long long)(base + myj) < out_elems)          out[base + myj] = hn;
                if ((long long)(base + H_DIM + myj) < out_elems)  out[base + H_DIM + myj] = hn;
            }
        }
        __syncthreads();

        // ---- arrive: release makes all CTA writes visible to acquirers ----
        if (tid == 0) {
            asm volatile("red.release.gpu.global.add.u32 [%0], %1;"
                         :: "l"(&g_sync), "r"(1u) : "memory");
        }
    }
}

// ============================================================
extern "C" void kernel_launch(void* const* d_in, const int* in_sizes, int n_in,
                              void* d_out, int out_size) {
    const float* x    = (const float*)d_in[0];
    const float* w_ih = (const float*)d_in[1];
    const float* w_hh = (const float*)d_in[2];
    const float* b_ih = (const float*)d_in[3];
    const float* b_hh = (const float*)d_in[4];
    float* out = (float*)d_out;

    gemm_gi_kernel<<<dim3(G3H / BN, L_SEQ / BM), 256>>>(x, w_ih, b_ih);
    gru_kernel<<<NCTA, 256>>>(w_hh, b_hh, out, out_size);
}

// round 4
// speedup vs baseline: 1.4686x; 1.2510x over previous
#include <cuda_runtime.h>
#include <cuda_fp16.h>
#include <math.h>

#define L_SEQ 2048
#define H_DIM 2048
#define G3H   6144
#define NCTA  128
#define TPB   512     // 16 warps; warp w owns j = cta*16 + w

// -------- device-global scratch (no allocations allowed) --------
__device__ float g_gi[(size_t)L_SEQ * G3H];        // 48 MB: x@W_ih^T + b_ih (+ b_hh for r,z)
__device__ __align__(16) __half g_h16[2][H_DIM];   // double-buffered fp16 h
__device__ unsigned int g_sync;                    // monotonic arrival counter

__device__ __forceinline__ __half2 u2h2(unsigned u) {
    return *reinterpret_cast<__half2*>(&u);
}

// ============================================================
// Kernel A: g_gi[t][r] = x[t]·w_ih[r] + b_ih[r] + (r<2H ? b_hh[r] : 0)
// b_hh folds into the sigmoid gates only; the n-gate's b_hh must stay
// inside the reset-gate product: n = tanh(i_n + r*(h·W_n + b_hh_n)).
// ============================================================
#define BM 64
#define BN 64
#define BK 16

__global__ void __launch_bounds__(256) gemm_gi_kernel(const float* __restrict__ X,
                                                      const float* __restrict__ W,
                                                      const float* __restrict__ b_ih,
                                                      const float* __restrict__ b_hh) {
    if (blockIdx.x == 0 && blockIdx.y == 0 && threadIdx.x == 0) g_sync = 0u;

    __shared__ float As[BK][BM + 4];
    __shared__ float Bs[BK][BN + 4];
    const int K = H_DIM;
    const int bm = blockIdx.y * BM;
    const int bn = blockIdx.x * BN;
    const int tid = threadIdx.x;
    const int tm = tid >> 4;
    const int tn = tid & 15;

    unsigned long long c[2][4];
#pragma unroll
    for (int i = 0; i < 2; i++)
#pragma unroll
        for (int j = 0; j < 4; j++) c[i][j] = 0ull;

    const int lrow = tid >> 2;
    const int lk   = (tid & 3) << 2;

    for (int k0 = 0; k0 < K; k0 += BK) {
        float4 av = *reinterpret_cast<const float4*>(&X[(size_t)(bm + lrow) * K + k0 + lk]);
        float4 bv = *reinterpret_cast<const float4*>(&W[(size_t)(bn + lrow) * K + k0 + lk]);
        As[lk + 0][lrow] = av.x; As[lk + 1][lrow] = av.y;
        As[lk + 2][lrow] = av.z; As[lk + 3][lrow] = av.w;
        Bs[lk + 0][lrow] = bv.x; Bs[lk + 1][lrow] = bv.y;
        Bs[lk + 2][lrow] = bv.z; Bs[lk + 3][lrow] = bv.w;
        __syncthreads();
#pragma unroll
        for (int k = 0; k < BK; k++) {
            float4 a = *reinterpret_cast<const float4*>(&As[k][tm << 2]);
            float4 b = *reinterpret_cast<const float4*>(&Bs[k][tn << 2]);
            unsigned long long a01, a23;
            asm("mov.b64 %0, {%1, %2};" : "=l"(a01) : "r"(__float_as_uint(a.x)), "r"(__float_as_uint(a.y)));
            asm("mov.b64 %0, {%1, %2};" : "=l"(a23) : "r"(__float_as_uint(a.z)), "r"(__float_as_uint(a.w)));
            float bj[4] = {b.x, b.y, b.z, b.w};
#pragma unroll
            for (int j = 0; j < 4; j++) {
                unsigned long long bb;
                asm("mov.b64 %0, {%1, %1};" : "=l"(bb) : "r"(__float_as_uint(bj[j])));
                asm("fma.rn.f32x2 %0, %1, %2, %0;" : "+l"(c[0][j]) : "l"(a01), "l"(bb));
                asm("fma.rn.f32x2 %0, %1, %2, %0;" : "+l"(c[1][j]) : "l"(a23), "l"(bb));
            }
        }
        __syncthreads();
    }
#pragma unroll
    for (int i2 = 0; i2 < 2; i2++) {
#pragma unroll
        for (int j = 0; j < 4; j++) {
            unsigned lo, hi;
            asm("mov.b64 {%0, %1}, %2;" : "=r"(lo), "=r"(hi) : "l"(c[i2][j]));
            int col  = bn + (tn << 2) + j;
            float bs = b_ih[col] + ((col < 2 * H_DIM) ? b_hh[col] : 0.0f);
            int row0 = bm + (tm << 2) + i2 * 2;
            g_gi[(size_t)row0 * G3H + col]       = __uint_as_float(lo) + bs;
            g_gi[(size_t)(row0 + 1) * G3H + col] = __uint_as_float(hi) + bs;
        }
    }
}

// ============================================================
// Kernel B: persistent GRU recurrence.
// 128 CTAs x 512 threads (16 warps). Warp w owns j = cta*16 + w:
// 3 gate rows, weights in 96 half2 registers per lane.
// Per step: gi prefetch -> poll -> stage h to SMEM (4KB, once per
// CTA) -> reg matvec (LDS h) -> butterfly reduce -> lane0 gates ->
// store h -> bar -> red.release arrive.
// ============================================================
__global__ void __launch_bounds__(TPB, 1) gru_kernel(const float* __restrict__ w_hh,
                                                     const float* __restrict__ b_hh,
                                                     float* __restrict__ out,
                                                     int out_elems) {
    __shared__ uint4 sH[H_DIM / 8];     // 2048 halfs = 4KB

    const int tid  = threadIdx.x;
    const int warp = tid >> 5;
    const int lane = tid & 31;
    const int j    = blockIdx.x * 16 + warp;

    // ---- prologue: 3 rows of W_hh into 96 half2 registers ----
    __half2 w[3][8][4];
#pragma unroll
    for (int g = 0; g < 3; g++) {
        const float* wr = w_hh + (size_t)(g * H_DIM + j) * H_DIM;
#pragma unroll
        for (int i = 0; i < 8; i++) {
            int k = i * 256 + lane * 8;
            float4 a = *reinterpret_cast<const float4*>(wr + k);
            float4 b = *reinterpret_cast<const float4*>(wr + k + 4);
            w[g][i][0] = __floats2half2_rn(a.x, a.y);
            w[g][i][1] = __floats2half2_rn(a.z, a.w);
            w[g][i][2] = __floats2half2_rn(b.x, b.y);
            w[g][i][3] = __floats2half2_rn(b.z, b.w);
        }
    }

    float h_own = 0.0f;
    const float bhn = (lane == 0) ? b_hh[2 * H_DIM + j] : 0.0f;  // n-gate recurrent bias
    const float* gi_ptr  = g_gi + j;
    float*       out_ptr = out + j;

    for (int t = 0; t < L_SEQ; t++) {
        // ---- gi prefetch: issued before poll, lands during the wait ----
        float ir = 0.f, iz = 0.f, inn = 0.f;
        if (lane == 0) {
            ir  = gi_ptr[0];
            iz  = gi_ptr[H_DIM];
            inn = gi_ptr[2 * H_DIM];
        }

        if (t > 0) {
            // ---- chip-wide wait for step t's h ----
            if (tid == 0) {
                unsigned target = (unsigned)t << 7;    // t * NCTA
                unsigned v;
                do {
                    asm volatile("ld.acquire.gpu.global.u32 %0, [%1];"
                                 : "=r"(v) : "l"(&g_sync) : "memory");
                } while (v < target);
            }
            __syncthreads();
            // ---- stage h into SMEM: 256 lanes x uint4 = 4KB ----
            if (tid < H_DIM / 8)
                sH[tid] = __ldcg(reinterpret_cast<const uint4*>(&g_h16[t & 1][0]) + tid);
            __syncthreads();
        }

        // ---- matvec: 3 rows, weights in regs, h from SMEM ----
        float acc[3] = {0.f, 0.f, 0.f};
        if (t > 0) {
#pragma unroll
            for (int ii = 0; ii < 4; ii++) {
                uint4 hv0 = sH[(2 * ii) * 32 + lane];
                uint4 hv1 = sH[(2 * ii + 1) * 32 + lane];
                __half2 a0 = u2h2(hv0.x), a1 = u2h2(hv0.y), a2 = u2h2(hv0.z), a3 = u2h2(hv0.w);
                __half2 b0 = u2h2(hv1.x), b1 = u2h2(hv1.y), b2 = u2h2(hv1.z), b3 = u2h2(hv1.w);
#pragma unroll
                for (int g = 0; g < 3; g++) {
                    __half2 s = __hmul2(w[g][2 * ii][0], a0);
                    s = __hfma2(w[g][2 * ii][1], a1, s);
                    s = __hfma2(w[g][2 * ii][2], a2, s);
                    s = __hfma2(w[g][2 * ii][3], a3, s);
                    s = __hfma2(w[g][2 * ii + 1][0], b0, s);
                    s = __hfma2(w[g][2 * ii + 1][1], b1, s);
                    s = __hfma2(w[g][2 * ii + 1][2], b2, s);
                    s = __hfma2(w[g][2 * ii + 1][3], b3, s);
                    float2 f = __half22float2(s);     // flush to fp32 every 16 MACs
                    acc[g] += f.x + f.y;
                }
            }
        }

        // ---- butterfly reduce over 32 lanes ----
#pragma unroll
        for (int off = 16; off; off >>= 1) {
#pragma unroll
            for (int g = 0; g < 3; g++)
                acc[g] += __shfl_xor_sync(0xffffffffu, acc[g], off);
        }

        // ---- gates + state update (lane 0) ----
        // r,z biases are folded into gi; n-gate's b_hh_n stays inside r*(...)
        if (lane == 0) {
            float rg = 1.0f / (1.0f + expf(-(ir + acc[0])));
            float zg = 1.0f / (1.0f + expf(-(iz + acc[1])));
            float ng = tanhf(inn + rg * (acc[2] + bhn));
            float hn = (1.0f - zg) * ng + zg * h_own;
            h_own = hn;
            out_ptr[0] = hn;
            g_h16[(t + 1) & 1][j] = __float2half(hn);
            if (t == L_SEQ - 1) {
                size_t base = (size_t)L_SEQ * H_DIM;
                if ((long long)(base + j) < out_elems)          out[base + j] = hn;
                if ((long long)(base + H_DIM + j) < out_elems)  out[base + H_DIM + j] = hn;
            }
        }
        __syncthreads();

        // ---- arrive ----
        if (tid == 0) {
            asm volatile("red.release.gpu.global.add.u32 [%0], %1;"
                         :: "l"(&g_sync), "r"(1u) : "memory");
        }

        gi_ptr  += G3H;
        out_ptr += H_DIM;
    }
}

// ============================================================
extern "C" void kernel_launch(void* const* d_in, const int* in_sizes, int n_in,
                              void* d_out, int out_size) {
    const float* x    = (const float*)d_in[0];
    const float* w_ih = (const float*)d_in[1];
    const float* w_hh = (const float*)d_in[2];
    const float* b_ih = (const float*)d_in[3];
    const float* b_hh = (const float*)d_in[4];
    float* out = (float*)d_out;

    gemm_gi_kernel<<<dim3(G3H / BN, L_SEQ / BM), 256>>>(x, w_ih, b_ih, b_hh);
    gru_kernel<<<NCTA, TPB>>>(w_hh, b_hh, out, out_size);
}